// round 13
// baseline (speedup 1.0000x reference)
#include <cuda_runtime.h>
#include <cuda_fp16.h>
#include <cstdint>

// ---------------- problem constants ----------------
#define T_TOK   2048
#define DDIM    1024
#define EXP     8
#define HDIM    4096
#define MT      128
#define ROUTED_CAP  5120
#define SHARED_BASE 5120
#define TOTAL_ROWS  7168
#define NMT     (TOTAL_ROWS / MT)         // 56
#define ROUTED_MT (ROUTED_CAP / MT)       // 40
#define EW_STRIDE (HDIM * DDIM)
#define PGRID   304                       // persistent CTAs (2 per SM)

// ---------------- device scratch ----------------
__device__ int   g_cnt[EXP];
__device__ int   g_fill[EXP];
__device__ int   g_segstart[EXP];
__device__ int   g_texp[NMT];
__device__ int   g_vt[NMT];
__device__ int   g_nv;
__device__ int   g_row_token[TOTAL_ROWS];
__device__ int   g_top_idx[T_TOK * 2];
__device__ float g_top_w[T_TOK * 2];
__device__ int   g_slot[T_TOK * 2];
__device__ __align__(16) __half g_xh[(size_t)TOTAL_ROWS * DDIM];
__device__ __align__(16) __half g_w1h[(size_t)(EXP + 1) * EW_STRIDE];
__device__ __align__(16) __half g_w2h[(size_t)(EXP + 1) * EW_STRIDE];
__device__ __align__(16) float  g_b1u[(EXP + 1) * HDIM];
__device__ __align__(16) float  g_b2u[(EXP + 1) * DDIM];
__device__ __align__(16) __half g_h[(size_t)TOTAL_ROWS * HDIM];
__device__ __align__(16) float  g_eo[2 * (size_t)TOTAL_ROWS * DDIM];

// ---------------- helpers ----------------
__device__ __forceinline__ float gelu_exact(float v) {
    return 0.5f * v * (1.0f + erff(v * 0.70710678118654752f));
}

__device__ __forceinline__ uint32_t smem_to_u32(const void* p) {
    uint32_t a;
    asm("{ .reg .u64 t; cvta.to.shared.u64 t, %1; cvt.u32.u64 %0, t; }" : "=r"(a) : "l"(p));
    return a;
}

__device__ __forceinline__ void ldsm_x4(uint32_t* r, uint32_t a) {
    asm volatile("ldmatrix.sync.aligned.m8n8.x4.shared.b16 {%0,%1,%2,%3}, [%4];\n"
                 : "=r"(r[0]), "=r"(r[1]), "=r"(r[2]), "=r"(r[3]) : "r"(a));
}

__device__ __forceinline__ void mma16816(float* c, const uint32_t* a, const uint32_t* b) {
    asm volatile(
        "mma.sync.aligned.m16n8k16.row.col.f32.f16.f16.f32 "
        "{%0,%1,%2,%3}, {%4,%5,%6,%7}, {%8,%9}, {%0,%1,%2,%3};\n"
        : "+f"(c[0]), "+f"(c[1]), "+f"(c[2]), "+f"(c[3])
        : "r"(a[0]), "r"(a[1]), "r"(a[2]), "r"(a[3]), "r"(b[0]), "r"(b[1]));
}

#define CP_ASYNC16(dst_u32, src_ptr) \
    asm volatile("cp.async.cg.shared.global [%0], [%1], 16;" :: "r"(dst_u32), "l"(src_ptr) : "memory")
#define CP_COMMIT() asm volatile("cp.async.commit_group;" ::: "memory")
#define CP_WAIT1()  asm volatile("cp.async.wait_group 1;" ::: "memory")

// ---------------- routing + staging kernels ----------------
__global__ void k_init(const float* __restrict__ b1, const float* __restrict__ bs1,
                       const float* __restrict__ b2, const float* __restrict__ bs2) {
    int i = blockIdx.x * blockDim.x + threadIdx.x;
    if (i < TOTAL_ROWS)
        g_row_token[i] = (i >= SHARED_BASE) ? (i - SHARED_BASE) : -1;
    if (i < EXP) { g_cnt[i] = 0; g_fill[i] = 0; }
    if (i < (EXP + 1) * HDIM)
        g_b1u[i] = (i < EXP * HDIM) ? b1[i] : bs1[i - EXP * HDIM];
    if (i < (EXP + 1) * DDIM)
        g_b2u[i] = (i < EXP * DDIM) ? b2[i] : bs2[i - EXP * DDIM];
}

__global__ void k_gate(const float* __restrict__ x, const float* __restrict__ Wg,
                       const float* __restrict__ bg, const float* __restrict__ bias) {
    int gwarp = (blockIdx.x * blockDim.x + threadIdx.x) >> 5;
    int lane  = threadIdx.x & 31;
    if (gwarp >= T_TOK) return;
    const float* xr = x + (size_t)gwarp * DDIM;
    float xs[32];
#pragma unroll
    for (int j = 0; j < 32; j++) xs[j] = xr[lane + 32 * j];
    float s[EXP];
#pragma unroll
    for (int e = 0; e < EXP; e++) {
        const float* wr = Wg + e * DDIM;
        float a = 0.f;
#pragma unroll
        for (int j = 0; j < 32; j++) a += xs[j] * wr[lane + 32 * j];
#pragma unroll
        for (int o = 16; o > 0; o >>= 1) a += __shfl_xor_sync(0xffffffffu, a, o);
        s[e] = 1.0f / (1.0f + expf(-(a + bg[e] + bias[e])));
    }
    if (lane == 0) {
        int i0 = 0; float v0 = s[0];
#pragma unroll
        for (int e = 1; e < EXP; e++) if (s[e] > v0) { v0 = s[e]; i0 = e; }
        int i1 = -1; float v1 = -1e30f;
#pragma unroll
        for (int e = 0; e < EXP; e++) if (e != i0 && s[e] > v1) { v1 = s[e]; i1 = e; }
        g_top_idx[2 * gwarp]     = i0; g_top_w[2 * gwarp]     = v0;
        g_top_idx[2 * gwarp + 1] = i1; g_top_w[2 * gwarp + 1] = v1;
        atomicAdd(&g_cnt[i0], 1);
        atomicAdd(&g_cnt[i1], 1);
    }
}

__global__ void k_seg() {
    if (threadIdx.x == 0 && blockIdx.x == 0) {
        int off = 0, nv = 0;
        for (int e = 0; e < EXP; e++) {
            g_segstart[e] = off;
            int tiles = (g_cnt[e] + MT - 1) / MT;
            for (int i = 0; i < tiles; i++) {
                int mt = off / MT + i;
                g_texp[mt] = e;
                g_vt[nv++] = mt;
            }
            off += tiles * MT;
        }
        for (int t = off / MT; t < ROUTED_MT; t++) g_texp[t] = -1;
        for (int t = ROUTED_MT; t < NMT; t++) { g_texp[t] = EXP; g_vt[nv++] = t; }
        g_nv = nv;
    }
}

__global__ void k_scatter() {
    int t = blockIdx.x * blockDim.x + threadIdx.x;
    if (t >= T_TOK) return;
#pragma unroll
    for (int k = 0; k < 2; k++) {
        int e = g_top_idx[2 * t + k];
        int pos = atomicAdd(&g_fill[e], 1);
        int row = g_segstart[e] + pos;
        g_slot[2 * t + k] = row;
        g_row_token[row]  = t;
    }
}

__global__ void k_xh(const float* __restrict__ x) {
    int r = blockIdx.x;
    int c = threadIdx.x * 8;
    int tok = g_row_token[r];
    __half* dst = g_xh + (size_t)r * DDIM + c;
    if (tok < 0) {
        *reinterpret_cast<uint4*>(dst) = make_uint4(0, 0, 0, 0);
        return;
    }
    const float* src = x + (size_t)tok * DDIM + c;
    float4 a = *reinterpret_cast<const float4*>(src);
    float4 b = *reinterpret_cast<const float4*>(src + 4);
    __half2 h0 = __floats2half2_rn(a.x, a.y), h1 = __floats2half2_rn(a.z, a.w);
    __half2 h2 = __floats2half2_rn(b.x, b.y), h3 = __floats2half2_rn(b.z, b.w);
    uint4 o;
    o.x = *reinterpret_cast<uint32_t*>(&h0); o.y = *reinterpret_cast<uint32_t*>(&h1);
    o.z = *reinterpret_cast<uint32_t*>(&h2); o.w = *reinterpret_cast<uint32_t*>(&h3);
    *reinterpret_cast<uint4*>(dst) = o;
}

// all four weight tensors converted by one kernel (flat index space)
__global__ void k_cvt_all(const float* __restrict__ W1, const float* __restrict__ Ws1,
                          const float* __restrict__ W2, const float* __restrict__ Ws2) {
    const size_t UN = (size_t)(EXP + 1) * EW_STRIDE;
    const size_t EE = (size_t)EXP * EW_STRIDE;
    size_t base = ((size_t)blockIdx.x * blockDim.x + threadIdx.x) * 8;
    const float* src; __half* dst;
    if (base < UN) {
        dst = g_w1h + base;
        src = (base < EE) ? (W1 + base) : (Ws1 + (base - EE));
    } else {
        size_t b = base - UN;
        dst = g_w2h + b;
        src = (b < EE) ? (W2 + b) : (Ws2 + (b - EE));
    }
    float4 a = *reinterpret_cast<const float4*>(src);
    float4 b4 = *reinterpret_cast<const float4*>(src + 4);
    __half2 h0 = __floats2half2_rn(a.x, a.y), h1 = __floats2half2_rn(a.z, a.w);
    __half2 h2 = __floats2half2_rn(b4.x, b4.y), h3 = __floats2half2_rn(b4.z, b4.w);
    uint4 o;
    o.x = *reinterpret_cast<uint32_t*>(&h0); o.y = *reinterpret_cast<uint32_t*>(&h1);
    o.z = *reinterpret_cast<uint32_t*>(&h2); o.w = *reinterpret_cast<uint32_t*>(&h3);
    *reinterpret_cast<uint4*>(dst) = o;
}

// ---------------- persistent fp16 grouped GEMM (K-chunk 64, 3 stages) ----------------
// CTA tile 128(M) x 128(N), 128 threads = 4 warps (2M x 2N of 64x64).
// K-chunk 64 halves: row = 144B (128B data + 16B pad). stage = (128+128)*144 = 36864B.
// 3 stages = 110592B/CTA -> 2 CTAs/SM. Half the barriers of the 32-K version.
#define STG   3
#define ROWB  144
#define BOFFS 18432
#define STGB  36864
#define GEMM_SMEM (STG * STGB)   // 110592

template <int KDIM, int NT, int NPART, bool DOGELU>
__global__ __launch_bounds__(128, 2) void k_gemm(
    const __half* __restrict__ A,      // [TOTAL_ROWS, KDIM] fp16
    const __half* __restrict__ W,      // [(EXP+1), NTOT, KDIM] fp16
    const float*  __restrict__ biasU,  // [(EXP+1), NTOT]
    int NTOT)
{
    constexpr int KPART = KDIM / NPART;
    constexpr int KT = KPART / 64;      // 16 (GEMM1) / 32 (GEMM2)
    extern __shared__ char smem[];
    const uint32_t sb = smem_to_u32(smem);

    const int tid = threadIdx.x, lane = tid & 31, warp = tid >> 5;
    const int wm = warp >> 1, wn = warp & 1;

    // cp.async bases: slot i covers rows (tid>>3)+16i, col chunk (tid&7)
    const uint32_t aoff0 = (tid >> 3) * ROWB + (tid & 7) * 16;           // smem bytes
    const uint32_t agl0  = (uint32_t)(tid >> 3) * KDIM + (tid & 7) * 8;  // global elems

    // ldmatrix base addrs (stage-relative)
    uint32_t a_ld[4], b_ld[4];
#pragma unroll
    for (int mi = 0; mi < 4; mi++) {
        int r = wm * 64 + mi * 16 + ((lane >> 3) & 1) * 8 + (lane & 7);
        a_ld[mi] = sb + r * ROWB + (lane >> 4) * 16;
    }
#pragma unroll
    for (int np = 0; np < 4; np++) {
        int r = wn * 64 + np * 16 + (lane >> 4) * 8 + (lane & 7);
        b_ld[np] = sb + BOFFS + r * ROWB + ((lane >> 3) & 1) * 16;
    }

    const int nv = g_nv;
    const int nitems = nv * NT * NPART;

    for (int it = blockIdx.x; it < nitems; it += gridDim.x) {
        int p  = it % NPART;
        int q  = it / NPART;
        int nt = q % NT;
        int v  = q / NT;
        int mt = g_vt[v];
        int e  = g_texp[mt];
        const int row0 = mt * MT;
        const int col0 = nt * 128;
        const __half* Ab = A + (size_t)row0 * KDIM + p * KPART;
        const __half* Wb = W + (size_t)e * NTOT * KDIM + (size_t)col0 * KDIM + p * KPART;

        auto LOAD = [&](int st, int ch) {
            uint32_t base = sb + st * STGB;
            uint32_t ko = ch * 64;
#pragma unroll
            for (int i = 0; i < 8; i++) {
                CP_ASYNC16(base + aoff0 + i * (16 * ROWB),
                           Ab + agl0 + (size_t)i * 16 * KDIM + ko);
                CP_ASYNC16(base + BOFFS + aoff0 + i * (16 * ROWB),
                           Wb + agl0 + (size_t)i * 16 * KDIM + ko);
            }
        };

        float acc[4][8][4];
#pragma unroll
        for (int mi = 0; mi < 4; mi++)
#pragma unroll
            for (int ni = 0; ni < 8; ni++)
#pragma unroll
                for (int j = 0; j < 4; j++) acc[mi][ni][j] = 0.f;

        LOAD(0, 0); CP_COMMIT();
        LOAD(1, 1); CP_COMMIT();

        int st = 0, lst = 2;
#pragma unroll 1
        for (int i = 0; i < KT; i++) {
            CP_WAIT1();
            __syncthreads();
            int j = i + 2;
            if (j < KT) LOAD(lst, j);
            CP_COMMIT();

            uint32_t so = st * STGB;
#pragma unroll
            for (int ks = 0; ks < 4; ks++) {          // 4 x 16-K steps per 64-K chunk
                uint32_t kb = so + ks * 32;
                uint32_t af[4][4], bf[8][2];
#pragma unroll
                for (int mi = 0; mi < 4; mi++) ldsm_x4(af[mi], a_ld[mi] + kb);
#pragma unroll
                for (int np = 0; np < 4; np++) {
                    uint32_t t4[4];
                    ldsm_x4(t4, b_ld[np] + kb);
                    bf[np * 2][0] = t4[0]; bf[np * 2][1] = t4[1];
                    bf[np * 2 + 1][0] = t4[2]; bf[np * 2 + 1][1] = t4[3];
                }
#pragma unroll
                for (int mi = 0; mi < 4; mi++)
#pragma unroll
                    for (int ni = 0; ni < 8; ni++)
                        mma16816(acc[mi][ni], af[mi], bf[ni]);
            }
            if (++st == STG) st = 0;
            if (++lst == STG) lst = 0;
        }
        // stage-reuse safety: next item's prologue stages overlap last chunk's stage
        __syncthreads();

        // epilogue
        const float* bias = biasU + e * NTOT;
        float* eout = g_eo + (size_t)p * TOTAL_ROWS * DDIM;
        bool addb = (p == 0);
#pragma unroll
        for (int mi = 0; mi < 4; mi++) {
#pragma unroll
            for (int ni = 0; ni < 8; ni++) {
                int gr = row0 + wm * 64 + mi * 16 + (lane >> 2);
                int gc = col0 + wn * 64 + ni * 8 + (lane & 3) * 2;
                if (DOGELU) {
                    float b0 = bias[gc], b1v = bias[gc + 1];
                    float v0 = gelu_exact(acc[mi][ni][0] + b0);
                    float v1 = gelu_exact(acc[mi][ni][1] + b1v);
                    *reinterpret_cast<__half2*>(&g_h[(size_t)gr * HDIM + gc]) =
                        __floats2half2_rn(v0, v1);
                    float v2 = gelu_exact(acc[mi][ni][2] + b0);
                    float v3 = gelu_exact(acc[mi][ni][3] + b1v);
                    *reinterpret_cast<__half2*>(&g_h[(size_t)(gr + 8) * HDIM + gc]) =
                        __floats2half2_rn(v2, v3);
                } else {
                    float b0 = addb ? bias[gc] : 0.f;
                    float b1v = addb ? bias[gc + 1] : 0.f;
                    float2 v01 = make_float2(acc[mi][ni][0] + b0, acc[mi][ni][1] + b1v);
                    float2 v23 = make_float2(acc[mi][ni][2] + b0, acc[mi][ni][3] + b1v);
                    *reinterpret_cast<float2*>(&eout[(size_t)gr * DDIM + gc]) = v01;
                    *reinterpret_cast<float2*>(&eout[(size_t)(gr + 8) * DDIM + gc]) = v23;
                }
            }
        }
    }
}

// ---------------- combine (sums split-K partials) ----------------
__global__ void k_combine(float* __restrict__ out) {
    int i = blockIdx.x * blockDim.x + threadIdx.x;
    if (i >= T_TOK * DDIM) return;
    int t = i >> 10;
    int d = i & (DDIM - 1);
    const float* e0 = g_eo;
    const float* e1 = g_eo + (size_t)TOTAL_ROWS * DDIM;
    size_t sr = (size_t)(SHARED_BASE + t) * DDIM + d;
    size_t s0 = (size_t)g_slot[2 * t]     * DDIM + d;
    size_t s1 = (size_t)g_slot[2 * t + 1] * DDIM + d;
    float v = (e0[sr] + e1[sr]);
    v += g_top_w[2 * t]     * (e0[s0] + e1[s0]);
    v += g_top_w[2 * t + 1] * (e0[s1] + e1[s1]);
    out[i] = v;
}

// ---------------- launch ----------------
extern "C" void kernel_launch(void* const* d_in, const int* in_sizes, int n_in,
                              void* d_out, int out_size) {
    const float* x    = (const float*)d_in[0];
    const float* Wg   = (const float*)d_in[1];
    const float* bg   = (const float*)d_in[2];
    const float* bias = (const float*)d_in[3];
    const float* W1   = (const float*)d_in[4];
    const float* b1   = (const float*)d_in[5];
    const float* W2   = (const float*)d_in[6];
    const float* b2   = (const float*)d_in[7];
    const float* Ws1  = (const float*)d_in[8];
    const float* bs1  = (const float*)d_in[9];
    const float* Ws2  = (const float*)d_in[10];
    const float* bs2  = (const float*)d_in[11];
    float* out = (float*)d_out;

    static bool attr_set = false;
    if (!attr_set) {
        cudaFuncSetAttribute(k_gemm<DDIM, HDIM / 128, 1, true>,
                             cudaFuncAttributeMaxDynamicSharedMemorySize, GEMM_SMEM);
        cudaFuncSetAttribute(k_gemm<HDIM, DDIM / 128, 2, false>,
                             cudaFuncAttributeMaxDynamicSharedMemorySize, GEMM_SMEM);
        attr_set = true;
    }

    __half* w1h; __half* w2h; __half* xh; __half* hh; float* b1u; float* b2u;
    cudaGetSymbolAddress((void**)&w1h, g_w1h);
    cudaGetSymbolAddress((void**)&w2h, g_w2h);
    cudaGetSymbolAddress((void**)&xh,  g_xh);
    cudaGetSymbolAddress((void**)&hh,  g_h);
    cudaGetSymbolAddress((void**)&b1u, g_b1u);
    cudaGetSymbolAddress((void**)&b2u, g_b2u);

    k_init<<<(EXP + 1) * HDIM / 256, 256>>>(b1, bs1, b2, bs2);
    k_gate<<<T_TOK * 32 / 256, 256>>>(x, Wg, bg, bias);
    k_seg<<<1, 32>>>();
    k_scatter<<<T_TOK / 256, 256>>>();
    k_xh<<<TOTAL_ROWS, 128>>>(x);
    k_cvt_all<<<(int)(2ull * (EXP + 1) * EW_STRIDE / 8 / 256), 256>>>(W1, Ws1, W2, Ws2);

    k_gemm<DDIM, HDIM / 128, 1, true ><<<PGRID, 128, GEMM_SMEM>>>(xh, w1h, b1u, HDIM);
    k_gemm<HDIM, DDIM / 128, 2, false><<<PGRID, 128, GEMM_SMEM>>>(hh, w2h, b2u, DDIM);

    k_combine<<<T_TOK * DDIM / 256, 256>>>(out);
}

// round 15
// speedup vs baseline: 1.0724x; 1.0724x over previous
#include <cuda_runtime.h>
#include <cuda_fp16.h>
#include <cstdint>

// ---------------- problem constants ----------------
#define T_TOK   2048
#define DDIM    1024
#define EXP     8
#define HDIM    4096
#define MT      128
#define ROUTED_CAP  5120
#define SHARED_BASE 5120
#define TOTAL_ROWS  7168
#define NMT     (TOTAL_ROWS / MT)         // 56
#define ROUTED_MT (ROUTED_CAP / MT)       // 40
#define EW_STRIDE (HDIM * DDIM)
#define PGRID   304                       // persistent CTAs (2 per SM)

// ---------------- device scratch ----------------
__device__ int   g_cnt[EXP];
__device__ int   g_fill[EXP];
__device__ int   g_segstart[EXP];
__device__ int   g_texp[NMT];
__device__ int   g_vt[NMT];
__device__ int   g_nv;
__device__ int   g_row_token[TOTAL_ROWS];
__device__ int   g_top_idx[T_TOK * 2];
__device__ float g_top_w[T_TOK * 2];
__device__ int   g_slot[T_TOK * 2];
__device__ __align__(16) __half g_xh[(size_t)TOTAL_ROWS * DDIM];
__device__ __align__(16) __half g_w1h[(size_t)(EXP + 1) * EW_STRIDE];
__device__ __align__(16) __half g_w2h[(size_t)(EXP + 1) * EW_STRIDE];
__device__ __align__(16) float  g_b1u[(EXP + 1) * HDIM];
__device__ __align__(16) float  g_b2u[(EXP + 1) * DDIM];
__device__ __align__(16) __half g_h[(size_t)TOTAL_ROWS * HDIM];
__device__ __align__(16) float  g_eo[2 * (size_t)TOTAL_ROWS * DDIM];

// ---------------- helpers ----------------
__device__ __forceinline__ float gelu_exact(float v) {
    return 0.5f * v * (1.0f + erff(v * 0.70710678118654752f));
}

__device__ __forceinline__ uint32_t smem_to_u32(const void* p) {
    uint32_t a;
    asm("{ .reg .u64 t; cvta.to.shared.u64 t, %1; cvt.u32.u64 %0, t; }" : "=r"(a) : "l"(p));
    return a;
}

__device__ __forceinline__ void ldsm_x4(uint32_t* r, uint32_t a) {
    asm volatile("ldmatrix.sync.aligned.m8n8.x4.shared.b16 {%0,%1,%2,%3}, [%4];\n"
                 : "=r"(r[0]), "=r"(r[1]), "=r"(r[2]), "=r"(r[3]) : "r"(a));
}

__device__ __forceinline__ void mma16816(float* c, const uint32_t* a, const uint32_t* b) {
    asm volatile(
        "mma.sync.aligned.m16n8k16.row.col.f32.f16.f16.f32 "
        "{%0,%1,%2,%3}, {%4,%5,%6,%7}, {%8,%9}, {%0,%1,%2,%3};\n"
        : "+f"(c[0]), "+f"(c[1]), "+f"(c[2]), "+f"(c[3])
        : "r"(a[0]), "r"(a[1]), "r"(a[2]), "r"(a[3]), "r"(b[0]), "r"(b[1]));
}

#define CP_ASYNC16(dst_u32, src_ptr) \
    asm volatile("cp.async.cg.shared.global [%0], [%1], 16;" :: "r"(dst_u32), "l"(src_ptr) : "memory")
#define CP_COMMIT() asm volatile("cp.async.commit_group;" ::: "memory")
#define CP_WAIT2()  asm volatile("cp.async.wait_group 2;" ::: "memory")

// ---------------- routing + staging kernels ----------------
__global__ void k_init(const float* __restrict__ b1, const float* __restrict__ bs1,
                       const float* __restrict__ b2, const float* __restrict__ bs2) {
    int i = blockIdx.x * blockDim.x + threadIdx.x;
    if (i < TOTAL_ROWS)
        g_row_token[i] = (i >= SHARED_BASE) ? (i - SHARED_BASE) : -1;
    if (i < EXP) { g_cnt[i] = 0; g_fill[i] = 0; }
    if (i < (EXP + 1) * HDIM)
        g_b1u[i] = (i < EXP * HDIM) ? b1[i] : bs1[i - EXP * HDIM];
    if (i < (EXP + 1) * DDIM)
        g_b2u[i] = (i < EXP * DDIM) ? b2[i] : bs2[i - EXP * DDIM];
}

__global__ void k_gate(const float* __restrict__ x, const float* __restrict__ Wg,
                       const float* __restrict__ bg, const float* __restrict__ bias) {
    int gwarp = (blockIdx.x * blockDim.x + threadIdx.x) >> 5;
    int lane  = threadIdx.x & 31;
    if (gwarp >= T_TOK) return;
    const float* xr = x + (size_t)gwarp * DDIM;
    float xs[32];
#pragma unroll
    for (int j = 0; j < 32; j++) xs[j] = xr[lane + 32 * j];
    float s[EXP];
#pragma unroll
    for (int e = 0; e < EXP; e++) {
        const float* wr = Wg + e * DDIM;
        float a = 0.f;
#pragma unroll
        for (int j = 0; j < 32; j++) a += xs[j] * wr[lane + 32 * j];
#pragma unroll
        for (int o = 16; o > 0; o >>= 1) a += __shfl_xor_sync(0xffffffffu, a, o);
        s[e] = 1.0f / (1.0f + expf(-(a + bg[e] + bias[e])));
    }
    if (lane == 0) {
        int i0 = 0; float v0 = s[0];
#pragma unroll
        for (int e = 1; e < EXP; e++) if (s[e] > v0) { v0 = s[e]; i0 = e; }
        int i1 = -1; float v1 = -1e30f;
#pragma unroll
        for (int e = 0; e < EXP; e++) if (e != i0 && s[e] > v1) { v1 = s[e]; i1 = e; }
        g_top_idx[2 * gwarp]     = i0; g_top_w[2 * gwarp]     = v0;
        g_top_idx[2 * gwarp + 1] = i1; g_top_w[2 * gwarp + 1] = v1;
        atomicAdd(&g_cnt[i0], 1);
        atomicAdd(&g_cnt[i1], 1);
    }
}

__global__ void k_seg() {
    if (threadIdx.x == 0 && blockIdx.x == 0) {
        int off = 0, nv = 0;
        for (int e = 0; e < EXP; e++) {
            g_segstart[e] = off;
            int tiles = (g_cnt[e] + MT - 1) / MT;
            for (int i = 0; i < tiles; i++) {
                int mt = off / MT + i;
                g_texp[mt] = e;
                g_vt[nv++] = mt;
            }
            off += tiles * MT;
        }
        for (int t = off / MT; t < ROUTED_MT; t++) g_texp[t] = -1;
        for (int t = ROUTED_MT; t < NMT; t++) { g_texp[t] = EXP; g_vt[nv++] = t; }
        g_nv = nv;
    }
}

__global__ void k_scatter() {
    int t = blockIdx.x * blockDim.x + threadIdx.x;
    if (t >= T_TOK) return;
#pragma unroll
    for (int k = 0; k < 2; k++) {
        int e = g_top_idx[2 * t + k];
        int pos = atomicAdd(&g_fill[e], 1);
        int row = g_segstart[e] + pos;
        g_slot[2 * t + k] = row;
        g_row_token[row]  = t;
    }
}

__global__ void k_xh(const float* __restrict__ x) {
    int r = blockIdx.x;
    int c = threadIdx.x * 8;
    int tok = g_row_token[r];
    __half* dst = g_xh + (size_t)r * DDIM + c;
    if (tok < 0) {
        *reinterpret_cast<uint4*>(dst) = make_uint4(0, 0, 0, 0);
        return;
    }
    const float* src = x + (size_t)tok * DDIM + c;
    float4 a = *reinterpret_cast<const float4*>(src);
    float4 b = *reinterpret_cast<const float4*>(src + 4);
    __half2 h0 = __floats2half2_rn(a.x, a.y), h1 = __floats2half2_rn(a.z, a.w);
    __half2 h2 = __floats2half2_rn(b.x, b.y), h3 = __floats2half2_rn(b.z, b.w);
    uint4 o;
    o.x = *reinterpret_cast<uint32_t*>(&h0); o.y = *reinterpret_cast<uint32_t*>(&h1);
    o.z = *reinterpret_cast<uint32_t*>(&h2); o.w = *reinterpret_cast<uint32_t*>(&h3);
    *reinterpret_cast<uint4*>(dst) = o;
}

// one weight set (expert + shared) -> fp16
__global__ void k_cvt(const float* __restrict__ We, const float* __restrict__ Ws,
                      __half* __restrict__ dst) {
    const size_t EE = (size_t)EXP * EW_STRIDE;
    size_t base = ((size_t)blockIdx.x * blockDim.x + threadIdx.x) * 8;
    const float* src = (base < EE) ? (We + base) : (Ws + (base - EE));
    float4 a = *reinterpret_cast<const float4*>(src);
    float4 b4 = *reinterpret_cast<const float4*>(src + 4);
    __half2 h0 = __floats2half2_rn(a.x, a.y), h1 = __floats2half2_rn(a.z, a.w);
    __half2 h2 = __floats2half2_rn(b4.x, b4.y), h3 = __floats2half2_rn(b4.z, b4.w);
    uint4 o;
    o.x = *reinterpret_cast<uint32_t*>(&h0); o.y = *reinterpret_cast<uint32_t*>(&h1);
    o.z = *reinterpret_cast<uint32_t*>(&h2); o.w = *reinterpret_cast<uint32_t*>(&h3);
    *reinterpret_cast<uint4*>(dst + base) = o;
}

// ---------------- persistent fp16 grouped GEMM (exact R6 config) ----------------
// CTA tile 128(M) x 128(N), 128 threads = 4 warps (2M x 2N of 64x64).
// K-chunk 32, 4-stage cp.async (wait_group 2). smem 81920B/CTA -> 2 CTAs/SM.
#define STG   4
#define STGB  20480
#define BOFFS 10240
#define GEMM_SMEM (STG * STGB)   // 81920

template <int KDIM, int NT, int NPART, bool DOGELU>
__global__ __launch_bounds__(128, 2) void k_gemm(
    const __half* __restrict__ A,      // [TOTAL_ROWS, KDIM] fp16
    const __half* __restrict__ W,      // [(EXP+1), NTOT, KDIM] fp16
    const float*  __restrict__ biasU,  // [(EXP+1), NTOT]
    int NTOT)
{
    constexpr int KPART = KDIM / NPART;
    constexpr int KT = KPART / 32;
    extern __shared__ char smem[];
    const uint32_t sb = smem_to_u32(smem);

    const int tid = threadIdx.x, lane = tid & 31, warp = tid >> 5;
    const int wm = warp >> 1, wn = warp & 1;

    // item-independent per-thread offsets (R6 layout)
    uint32_t agl[4], aoff[4], bgl[4], boff[4];
#pragma unroll
    for (int i = 0; i < 4; i++) {
        int l = tid + i * 128;            // 0..511
        int r = l >> 2, c8 = l & 3;       // r 0..127, 4 x 16B chunks per row
        agl[i]  = (uint32_t)r * KDIM + c8 * 8;
        aoff[i] = r * 80 + c8 * 16;
        bgl[i]  = agl[i];
        boff[i] = BOFFS + r * 80 + c8 * 16;
    }
    uint32_t a_ld[4], b_ld[4];
#pragma unroll
    for (int mi = 0; mi < 4; mi++) {
        int r = wm * 64 + mi * 16 + ((lane >> 3) & 1) * 8 + (lane & 7);
        a_ld[mi] = sb + r * 80 + (lane >> 4) * 16;
    }
#pragma unroll
    for (int np = 0; np < 4; np++) {
        int r = wn * 64 + np * 16 + (lane >> 4) * 8 + (lane & 7);
        b_ld[np] = sb + BOFFS + r * 80 + ((lane >> 3) & 1) * 16;
    }

    const int nv = g_nv;
    const int nitems = nv * NT * NPART;

    for (int it = blockIdx.x; it < nitems; it += gridDim.x) {
        int p  = it % NPART;
        int q  = it / NPART;
        int nt = q % NT;
        int v  = q / NT;
        int mt = g_vt[v];
        int e  = g_texp[mt];
        const int row0 = mt * MT;
        const int col0 = nt * 128;
        const __half* Ab = A + (size_t)row0 * KDIM + p * KPART;
        const __half* Wb = W + (size_t)e * NTOT * KDIM + (size_t)col0 * KDIM + p * KPART;

        float acc[4][8][4];
#pragma unroll
        for (int mi = 0; mi < 4; mi++)
#pragma unroll
            for (int ni = 0; ni < 8; ni++)
#pragma unroll
                for (int j = 0; j < 4; j++) acc[mi][ni][j] = 0.f;

        auto LOAD = [&](int st, int ch) {
            uint32_t base = sb + st * STGB;
            uint32_t koff = ch * 32;
#pragma unroll
            for (int i = 0; i < 4; i++) CP_ASYNC16(base + aoff[i], Ab + agl[i] + koff);
#pragma unroll
            for (int i = 0; i < 4; i++) CP_ASYNC16(base + boff[i], Wb + bgl[i] + koff);
        };

#pragma unroll
        for (int c = 0; c < STG - 1; c++) { LOAD(c, c); CP_COMMIT(); }

#pragma unroll 1
        for (int i = 0; i < KT; i++) {
            CP_WAIT2();
            __syncthreads();
            int j = i + STG - 1;
            if (j < KT) LOAD(j & (STG - 1), j);
            CP_COMMIT();

            uint32_t so = (i & (STG - 1)) * STGB;
#pragma unroll
            for (int ks = 0; ks < 2; ks++) {
                uint32_t kb = so + ks * 32;
                uint32_t af[4][4], bf[8][2];
#pragma unroll
                for (int mi = 0; mi < 4; mi++) ldsm_x4(af[mi], a_ld[mi] + kb);
#pragma unroll
                for (int np = 0; np < 4; np++) {
                    uint32_t t4[4];
                    ldsm_x4(t4, b_ld[np] + kb);
                    bf[np * 2][0] = t4[0]; bf[np * 2][1] = t4[1];
                    bf[np * 2 + 1][0] = t4[2]; bf[np * 2 + 1][1] = t4[3];
                }
#pragma unroll
                for (int mi = 0; mi < 4; mi++)
#pragma unroll
                    for (int ni = 0; ni < 8; ni++)
                        mma16816(acc[mi][ni], af[mi], bf[ni]);
            }
        }

        // epilogue (stage reuse across items safe: last chunk stage = 3, prologue uses 0..2,
        // and the per-iteration barriers bound warp drift to one interval)
        const float* bias = biasU + e * NTOT;
        float* eout = g_eo + (size_t)p * TOTAL_ROWS * DDIM;
        bool addb = (p == 0);
#pragma unroll
        for (int mi = 0; mi < 4; mi++) {
#pragma unroll
            for (int ni = 0; ni < 8; ni++) {
                int gr = row0 + wm * 64 + mi * 16 + (lane >> 2);
                int gc = col0 + wn * 64 + ni * 8 + (lane & 3) * 2;
                if (DOGELU) {
                    float b0 = bias[gc], b1v = bias[gc + 1];
                    float v0 = gelu_exact(acc[mi][ni][0] + b0);
                    float v1 = gelu_exact(acc[mi][ni][1] + b1v);
                    *reinterpret_cast<__half2*>(&g_h[(size_t)gr * HDIM + gc]) =
                        __floats2half2_rn(v0, v1);
                    float v2 = gelu_exact(acc[mi][ni][2] + b0);
                    float v3 = gelu_exact(acc[mi][ni][3] + b1v);
                    *reinterpret_cast<__half2*>(&g_h[(size_t)(gr + 8) * HDIM + gc]) =
                        __floats2half2_rn(v2, v3);
                } else {
                    float b0 = addb ? bias[gc] : 0.f;
                    float b1v = addb ? bias[gc + 1] : 0.f;
                    float2 v01 = make_float2(acc[mi][ni][0] + b0, acc[mi][ni][1] + b1v);
                    float2 v23 = make_float2(acc[mi][ni][2] + b0, acc[mi][ni][3] + b1v);
                    *reinterpret_cast<float2*>(&eout[(size_t)gr * DDIM + gc]) = v01;
                    *reinterpret_cast<float2*>(&eout[(size_t)(gr + 8) * DDIM + gc]) = v23;
                }
            }
        }
    }
}

// ---------------- combine (sums split-K partials) ----------------
__global__ void k_combine(float* __restrict__ out) {
    int i = blockIdx.x * blockDim.x + threadIdx.x;
    if (i >= T_TOK * DDIM) return;
    int t = i >> 10;
    int d = i & (DDIM - 1);
    const float* e0 = g_eo;
    const float* e1 = g_eo + (size_t)TOTAL_ROWS * DDIM;
    size_t sr = (size_t)(SHARED_BASE + t) * DDIM + d;
    size_t s0 = (size_t)g_slot[2 * t]     * DDIM + d;
    size_t s1 = (size_t)g_slot[2 * t + 1] * DDIM + d;
    float v = (e0[sr] + e1[sr]);
    v += g_top_w[2 * t]     * (e0[s0] + e1[s0]);
    v += g_top_w[2 * t + 1] * (e0[s1] + e1[s1]);
    out[i] = v;
}

// ---------------- launch ----------------
extern "C" void kernel_launch(void* const* d_in, const int* in_sizes, int n_in,
                              void* d_out, int out_size) {
    const float* x    = (const float*)d_in[0];
    const float* Wg   = (const float*)d_in[1];
    const float* bg   = (const float*)d_in[2];
    const float* bias = (const float*)d_in[3];
    const float* W1   = (const float*)d_in[4];
    const float* b1   = (const float*)d_in[5];
    const float* W2   = (const float*)d_in[6];
    const float* b2   = (const float*)d_in[7];
    const float* Ws1  = (const float*)d_in[8];
    const float* bs1  = (const float*)d_in[9];
    const float* Ws2  = (const float*)d_in[10];
    const float* bs2  = (const float*)d_in[11];
    float* out = (float*)d_out;

    static bool init_done = false;
    static cudaStream_t s1 = nullptr;
    static cudaEvent_t evF = nullptr, ev1 = nullptr, ev2 = nullptr;
    if (!init_done) {
        cudaFuncSetAttribute(k_gemm<DDIM, HDIM / 128, 1, true>,
                             cudaFuncAttributeMaxDynamicSharedMemorySize, GEMM_SMEM);
        cudaFuncSetAttribute(k_gemm<HDIM, DDIM / 128, 2, false>,
                             cudaFuncAttributeMaxDynamicSharedMemorySize, GEMM_SMEM);
        cudaStreamCreateWithFlags(&s1, cudaStreamNonBlocking);
        cudaEventCreateWithFlags(&evF, cudaEventDisableTiming);
        cudaEventCreateWithFlags(&ev1, cudaEventDisableTiming);
        cudaEventCreateWithFlags(&ev2, cudaEventDisableTiming);
        init_done = true;
    }

    __half* w1h; __half* w2h; __half* xh; __half* hh; float* b1u; float* b2u;
    cudaGetSymbolAddress((void**)&w1h, g_w1h);
    cudaGetSymbolAddress((void**)&w2h, g_w2h);
    cudaGetSymbolAddress((void**)&xh,  g_xh);
    cudaGetSymbolAddress((void**)&hh,  g_h);
    cudaGetSymbolAddress((void**)&b1u, g_b1u);
    cudaGetSymbolAddress((void**)&b2u, g_b2u);

    const int CVT_GRID = (int)((size_t)(EXP + 1) * EW_STRIDE / 8 / 256);  // 18432

    // fork: weight conversions on side stream, routing on main stream
    cudaEventRecord(evF, 0);
    cudaStreamWaitEvent(s1, evF, 0);
    k_cvt<<<CVT_GRID, 256, 0, s1>>>(W1, Ws1, w1h);
    cudaEventRecord(ev1, s1);
    k_cvt<<<CVT_GRID, 256, 0, s1>>>(W2, Ws2, w2h);
    cudaEventRecord(ev2, s1);

    k_init<<<(EXP + 1) * HDIM / 256, 256>>>(b1, bs1, b2, bs2);
    k_gate<<<T_TOK * 32 / 256, 256>>>(x, Wg, bg, bias);
    k_seg<<<1, 32>>>();
    k_scatter<<<T_TOK / 256, 256>>>();
    k_xh<<<TOTAL_ROWS, 128>>>(x);

    // join: GEMM1 needs W1h; GEMM2 needs W2h
    cudaStreamWaitEvent(0, ev1, 0);
    k_gemm<DDIM, HDIM / 128, 1, true ><<<PGRID, 128, GEMM_SMEM>>>(xh, w1h, b1u, HDIM);
    cudaStreamWaitEvent(0, ev2, 0);
    k_gemm<HDIM, DDIM / 128, 2, false><<<PGRID, 128, GEMM_SMEM>>>(hh, w2h, b2u, DDIM);

    k_combine<<<T_TOK * DDIM / 256, 256>>>(out);
}

// round 16
// speedup vs baseline: 1.0794x; 1.0065x over previous
#include <cuda_runtime.h>
#include <cuda_fp16.h>
#include <cstdint>

// ---------------- problem constants ----------------
#define T_TOK   2048
#define DDIM    1024
#define EXP     8
#define HDIM    4096
#define MT      128
#define ROUTED_CAP  5120
#define SHARED_BASE 5120
#define TOTAL_ROWS  7168
#define NMT     (TOTAL_ROWS / MT)         // 56
#define ROUTED_MT (ROUTED_CAP / MT)       // 40
#define EW_STRIDE (HDIM * DDIM)
#define PGRID   304                       // persistent CTAs (2 per SM)

// ---------------- device scratch ----------------
__device__ int   g_cnt[EXP];
__device__ int   g_fill[EXP];
__device__ int   g_segstart[EXP];
__device__ int   g_texp[NMT];
__device__ int   g_vt[NMT];
__device__ int   g_nv;
__device__ int   g_row_token[TOTAL_ROWS];
__device__ float g_row_w[TOTAL_ROWS];
__device__ int   g_top_idx[T_TOK * 2];
__device__ float g_top_w[T_TOK * 2];
__device__ __align__(16) __half g_xh[(size_t)TOTAL_ROWS * DDIM];
__device__ __align__(16) __half g_w1h[(size_t)(EXP + 1) * EW_STRIDE];
__device__ __align__(16) __half g_w2h[(size_t)(EXP + 1) * EW_STRIDE];
__device__ __align__(16) float  g_b1u[(EXP + 1) * HDIM];
__device__ __align__(16) float  g_b2u[(EXP + 1) * DDIM];
__device__ __align__(16) __half g_h[(size_t)TOTAL_ROWS * HDIM];

// ---------------- helpers ----------------
__device__ __forceinline__ float gelu_exact(float v) {
    return 0.5f * v * (1.0f + erff(v * 0.70710678118654752f));
}

__device__ __forceinline__ uint32_t smem_to_u32(const void* p) {
    uint32_t a;
    asm("{ .reg .u64 t; cvta.to.shared.u64 t, %1; cvt.u32.u64 %0, t; }" : "=r"(a) : "l"(p));
    return a;
}

__device__ __forceinline__ void ldsm_x4(uint32_t* r, uint32_t a) {
    asm volatile("ldmatrix.sync.aligned.m8n8.x4.shared.b16 {%0,%1,%2,%3}, [%4];\n"
                 : "=r"(r[0]), "=r"(r[1]), "=r"(r[2]), "=r"(r[3]) : "r"(a));
}

__device__ __forceinline__ void mma16816(float* c, const uint32_t* a, const uint32_t* b) {
    asm volatile(
        "mma.sync.aligned.m16n8k16.row.col.f32.f16.f16.f32 "
        "{%0,%1,%2,%3}, {%4,%5,%6,%7}, {%8,%9}, {%0,%1,%2,%3};\n"
        : "+f"(c[0]), "+f"(c[1]), "+f"(c[2]), "+f"(c[3])
        : "r"(a[0]), "r"(a[1]), "r"(a[2]), "r"(a[3]), "r"(b[0]), "r"(b[1]));
}

#define CP_ASYNC16(dst_u32, src_ptr) \
    asm volatile("cp.async.cg.shared.global [%0], [%1], 16;" :: "r"(dst_u32), "l"(src_ptr) : "memory")
#define CP_COMMIT() asm volatile("cp.async.commit_group;" ::: "memory")
#define CP_WAIT2()  asm volatile("cp.async.wait_group 2;" ::: "memory")

// ---------------- routing + staging kernels ----------------
__global__ void k_init(const float* __restrict__ b1, const float* __restrict__ bs1,
                       const float* __restrict__ b2, const float* __restrict__ bs2,
                       float* __restrict__ out) {
    int i = blockIdx.x * blockDim.x + threadIdx.x;
    if (i < TOTAL_ROWS) {
        g_row_token[i] = (i >= SHARED_BASE) ? (i - SHARED_BASE) : -1;
        g_row_w[i]     = (i >= SHARED_BASE) ? 1.0f : 0.0f;
    }
    if (i < EXP) { g_cnt[i] = 0; g_fill[i] = 0; }
    if (i < (EXP + 1) * HDIM)
        g_b1u[i] = (i < EXP * HDIM) ? b1[i] : bs1[i - EXP * HDIM];
    if (i < (EXP + 1) * DDIM)
        g_b2u[i] = (i < EXP * DDIM) ? b2[i] : bs2[i - EXP * DDIM];
    if (i < T_TOK * DDIM / 4)
        *reinterpret_cast<float4*>(out + i * 4) = make_float4(0.f, 0.f, 0.f, 0.f);
}

// vectorized gating: 8 x LDG.128 per thread for x and per expert row of Wg
__global__ void k_gate(const float* __restrict__ x, const float* __restrict__ Wg,
                       const float* __restrict__ bg, const float* __restrict__ bias) {
    int gwarp = (blockIdx.x * blockDim.x + threadIdx.x) >> 5;
    int lane  = threadIdx.x & 31;
    if (gwarp >= T_TOK) return;
    const float* xr = x + (size_t)gwarp * DDIM;
    float4 xs[8];
#pragma unroll
    for (int j = 0; j < 8; j++)
        xs[j] = *reinterpret_cast<const float4*>(&xr[lane * 4 + j * 128]);
    float s[EXP];
#pragma unroll
    for (int e = 0; e < EXP; e++) {
        const float* wr = Wg + e * DDIM;
        float a = 0.f;
#pragma unroll
        for (int j = 0; j < 8; j++) {
            float4 w4 = *reinterpret_cast<const float4*>(&wr[lane * 4 + j * 128]);
            a += xs[j].x * w4.x + xs[j].y * w4.y + xs[j].z * w4.z + xs[j].w * w4.w;
        }
#pragma unroll
        for (int o = 16; o > 0; o >>= 1) a += __shfl_xor_sync(0xffffffffu, a, o);
        s[e] = 1.0f / (1.0f + expf(-(a + bg[e] + bias[e])));
    }
    if (lane == 0) {
        int i0 = 0; float v0 = s[0];
#pragma unroll
        for (int e = 1; e < EXP; e++) if (s[e] > v0) { v0 = s[e]; i0 = e; }
        int i1 = -1; float v1 = -1e30f;
#pragma unroll
        for (int e = 0; e < EXP; e++) if (e != i0 && s[e] > v1) { v1 = s[e]; i1 = e; }
        g_top_idx[2 * gwarp]     = i0; g_top_w[2 * gwarp]     = v0;
        g_top_idx[2 * gwarp + 1] = i1; g_top_w[2 * gwarp + 1] = v1;
        atomicAdd(&g_cnt[i0], 1);
        atomicAdd(&g_cnt[i1], 1);
    }
}

__global__ void k_seg() {
    if (threadIdx.x == 0 && blockIdx.x == 0) {
        int off = 0, nv = 0;
        for (int e = 0; e < EXP; e++) {
            g_segstart[e] = off;
            int tiles = (g_cnt[e] + MT - 1) / MT;
            for (int i = 0; i < tiles; i++) {
                int mt = off / MT + i;
                g_texp[mt] = e;
                g_vt[nv++] = mt;
            }
            off += tiles * MT;
        }
        for (int t = off / MT; t < ROUTED_MT; t++) g_texp[t] = -1;
        for (int t = ROUTED_MT; t < NMT; t++) { g_texp[t] = EXP; g_vt[nv++] = t; }
        g_nv = nv;
    }
}

__global__ void k_scatter() {
    int t = blockIdx.x * blockDim.x + threadIdx.x;
    if (t >= T_TOK) return;
#pragma unroll
    for (int k = 0; k < 2; k++) {
        int e = g_top_idx[2 * t + k];
        int pos = atomicAdd(&g_fill[e], 1);
        int row = g_segstart[e] + pos;
        g_row_token[row] = t;
        g_row_w[row]     = g_top_w[2 * t + k];
    }
}

__global__ void k_xh(const float* __restrict__ x) {
    int r = blockIdx.x;
    int c = threadIdx.x * 8;
    int tok = g_row_token[r];
    __half* dst = g_xh + (size_t)r * DDIM + c;
    if (tok < 0) {
        *reinterpret_cast<uint4*>(dst) = make_uint4(0, 0, 0, 0);
        return;
    }
    const float* src = x + (size_t)tok * DDIM + c;
    float4 a = *reinterpret_cast<const float4*>(src);
    float4 b = *reinterpret_cast<const float4*>(src + 4);
    __half2 h0 = __floats2half2_rn(a.x, a.y), h1 = __floats2half2_rn(a.z, a.w);
    __half2 h2 = __floats2half2_rn(b.x, b.y), h3 = __floats2half2_rn(b.z, b.w);
    uint4 o;
    o.x = *reinterpret_cast<uint32_t*>(&h0); o.y = *reinterpret_cast<uint32_t*>(&h1);
    o.z = *reinterpret_cast<uint32_t*>(&h2); o.w = *reinterpret_cast<uint32_t*>(&h3);
    *reinterpret_cast<uint4*>(dst) = o;
}

// one weight set (expert + shared) -> fp16
__global__ void k_cvt(const float* __restrict__ We, const float* __restrict__ Ws,
                      __half* __restrict__ dst) {
    const size_t EE = (size_t)EXP * EW_STRIDE;
    size_t base = ((size_t)blockIdx.x * blockDim.x + threadIdx.x) * 8;
    const float* src = (base < EE) ? (We + base) : (Ws + (base - EE));
    float4 a = *reinterpret_cast<const float4*>(src);
    float4 b4 = *reinterpret_cast<const float4*>(src + 4);
    __half2 h0 = __floats2half2_rn(a.x, a.y), h1 = __floats2half2_rn(a.z, a.w);
    __half2 h2 = __floats2half2_rn(b4.x, b4.y), h3 = __floats2half2_rn(b4.z, b4.w);
    uint4 o;
    o.x = *reinterpret_cast<uint32_t*>(&h0); o.y = *reinterpret_cast<uint32_t*>(&h1);
    o.z = *reinterpret_cast<uint32_t*>(&h2); o.w = *reinterpret_cast<uint32_t*>(&h3);
    *reinterpret_cast<uint4*>(dst + base) = o;
}

// ---------------- persistent fp16 grouped GEMM (R6 mainloop, fused-out epilogue) ----------------
// CTA tile 128(M) x 128(N), 128 threads = 4 warps (2M x 2N of 64x64).
// K-chunk 32, 4-stage cp.async (wait_group 2). smem 81920B/CTA -> 2 CTAs/SM.
// DOGELU=true  : h = gelu(acc + b1) -> g_h (fp16)
// DOGELU=false : atomicAdd(out[token], row_w * (acc + bias@p0))  — combine fused.
#define STG   4
#define STGB  20480
#define BOFFS 10240
#define GEMM_SMEM (STG * STGB)   // 81920

template <int KDIM, int NT, int NPART, bool DOGELU>
__global__ __launch_bounds__(128, 2) void k_gemm(
    const __half* __restrict__ A,      // [TOTAL_ROWS, KDIM] fp16
    const __half* __restrict__ W,      // [(EXP+1), NTOT, KDIM] fp16
    const float*  __restrict__ biasU,  // [(EXP+1), NTOT]
    float* __restrict__ out,           // fused combine target (GEMM2 only)
    int NTOT)
{
    constexpr int KPART = KDIM / NPART;
    constexpr int KT = KPART / 32;
    extern __shared__ char smem[];
    const uint32_t sb = smem_to_u32(smem);

    const int tid = threadIdx.x, lane = tid & 31, warp = tid >> 5;
    const int wm = warp >> 1, wn = warp & 1;

    // item-independent per-thread offsets (R6 layout)
    uint32_t agl[4], aoff[4], bgl[4], boff[4];
#pragma unroll
    for (int i = 0; i < 4; i++) {
        int l = tid + i * 128;            // 0..511
        int r = l >> 2, c8 = l & 3;       // r 0..127, 4 x 16B chunks per row
        agl[i]  = (uint32_t)r * KDIM + c8 * 8;
        aoff[i] = r * 80 + c8 * 16;
        bgl[i]  = agl[i];
        boff[i] = BOFFS + r * 80 + c8 * 16;
    }
    uint32_t a_ld[4], b_ld[4];
#pragma unroll
    for (int mi = 0; mi < 4; mi++) {
        int r = wm * 64 + mi * 16 + ((lane >> 3) & 1) * 8 + (lane & 7);
        a_ld[mi] = sb + r * 80 + (lane >> 4) * 16;
    }
#pragma unroll
    for (int np = 0; np < 4; np++) {
        int r = wn * 64 + np * 16 + (lane >> 4) * 8 + (lane & 7);
        b_ld[np] = sb + BOFFS + r * 80 + ((lane >> 3) & 1) * 16;
    }

    const int nv = g_nv;
    const int nitems = nv * NT * NPART;

    for (int it = blockIdx.x; it < nitems; it += gridDim.x) {
        int p  = it % NPART;
        int q  = it / NPART;
        int nt = q % NT;
        int v  = q / NT;
        int mt = g_vt[v];
        int e  = g_texp[mt];
        const int row0 = mt * MT;
        const int col0 = nt * 128;
        const __half* Ab = A + (size_t)row0 * KDIM + p * KPART;
        const __half* Wb = W + (size_t)e * NTOT * KDIM + (size_t)col0 * KDIM + p * KPART;

        float acc[4][8][4];
#pragma unroll
        for (int mi = 0; mi < 4; mi++)
#pragma unroll
            for (int ni = 0; ni < 8; ni++)
#pragma unroll
                for (int j = 0; j < 4; j++) acc[mi][ni][j] = 0.f;

        auto LOAD = [&](int st, int ch) {
            uint32_t base = sb + st * STGB;
            uint32_t koff = ch * 32;
#pragma unroll
            for (int i = 0; i < 4; i++) CP_ASYNC16(base + aoff[i], Ab + agl[i] + koff);
#pragma unroll
            for (int i = 0; i < 4; i++) CP_ASYNC16(base + boff[i], Wb + bgl[i] + koff);
        };

#pragma unroll
        for (int c = 0; c < STG - 1; c++) { LOAD(c, c); CP_COMMIT(); }

#pragma unroll 1
        for (int i = 0; i < KT; i++) {
            CP_WAIT2();
            __syncthreads();
            int j = i + STG - 1;
            if (j < KT) LOAD(j & (STG - 1), j);
            CP_COMMIT();

            uint32_t so = (i & (STG - 1)) * STGB;
#pragma unroll
            for (int ks = 0; ks < 2; ks++) {
                uint32_t kb = so + ks * 32;
                uint32_t af[4][4], bf[8][2];
#pragma unroll
                for (int mi = 0; mi < 4; mi++) ldsm_x4(af[mi], a_ld[mi] + kb);
#pragma unroll
                for (int np = 0; np < 4; np++) {
                    uint32_t t4[4];
                    ldsm_x4(t4, b_ld[np] + kb);
                    bf[np * 2][0] = t4[0]; bf[np * 2][1] = t4[1];
                    bf[np * 2 + 1][0] = t4[2]; bf[np * 2 + 1][1] = t4[3];
                }
#pragma unroll
                for (int mi = 0; mi < 4; mi++)
#pragma unroll
                    for (int ni = 0; ni < 8; ni++)
                        mma16816(acc[mi][ni], af[mi], bf[ni]);
            }
        }

        // epilogue (stage reuse across items safe: last chunk stage = 3, prologue uses 0..2,
        // and the per-iteration barriers bound warp drift to one interval)
        const float* bias = biasU + e * NTOT;
        bool addb = (p == 0);
#pragma unroll
        for (int mi = 0; mi < 4; mi++) {
            int r0 = row0 + wm * 64 + mi * 16 + (lane >> 2);
            int tok0, tok1; float w0, w1;
            if (!DOGELU) {
                tok0 = g_row_token[r0];     w0 = g_row_w[r0];
                tok1 = g_row_token[r0 + 8]; w1 = g_row_w[r0 + 8];
            }
#pragma unroll
            for (int ni = 0; ni < 8; ni++) {
                int gc = col0 + wn * 64 + ni * 8 + (lane & 3) * 2;
                if (DOGELU) {
                    float b0 = bias[gc], b1v = bias[gc + 1];
                    float v0 = gelu_exact(acc[mi][ni][0] + b0);
                    float v1 = gelu_exact(acc[mi][ni][1] + b1v);
                    *reinterpret_cast<__half2*>(&g_h[(size_t)r0 * HDIM + gc]) =
                        __floats2half2_rn(v0, v1);
                    float v2 = gelu_exact(acc[mi][ni][2] + b0);
                    float v3 = gelu_exact(acc[mi][ni][3] + b1v);
                    *reinterpret_cast<__half2*>(&g_h[(size_t)(r0 + 8) * HDIM + gc]) =
                        __floats2half2_rn(v2, v3);
                } else {
                    float b0 = addb ? bias[gc] : 0.f;
                    float b1v = addb ? bias[gc + 1] : 0.f;
                    if (tok0 >= 0) {
                        float* o = out + (size_t)tok0 * DDIM + gc;
                        atomicAdd(o,     w0 * (acc[mi][ni][0] + b0));
                        atomicAdd(o + 1, w0 * (acc[mi][ni][1] + b1v));
                    }
                    if (tok1 >= 0) {
                        float* o = out + (size_t)tok1 * DDIM + gc;
                        atomicAdd(o,     w1 * (acc[mi][ni][2] + b0));
                        atomicAdd(o + 1, w1 * (acc[mi][ni][3] + b1v));
                    }
                }
            }
        }
    }
}

// ---------------- launch ----------------
extern "C" void kernel_launch(void* const* d_in, const int* in_sizes, int n_in,
                              void* d_out, int out_size) {
    const float* x    = (const float*)d_in[0];
    const float* Wg   = (const float*)d_in[1];
    const float* bg   = (const float*)d_in[2];
    const float* bias = (const float*)d_in[3];
    const float* W1   = (const float*)d_in[4];
    const float* b1   = (const float*)d_in[5];
    const float* W2   = (const float*)d_in[6];
    const float* b2   = (const float*)d_in[7];
    const float* Ws1  = (const float*)d_in[8];
    const float* bs1  = (const float*)d_in[9];
    const float* Ws2  = (const float*)d_in[10];
    const float* bs2  = (const float*)d_in[11];
    float* out = (float*)d_out;

    static bool init_done = false;
    static cudaStream_t s1 = nullptr;
    static cudaEvent_t evF = nullptr, ev1 = nullptr, ev2 = nullptr;
    if (!init_done) {
        cudaFuncSetAttribute(k_gemm<DDIM, HDIM / 128, 1, true>,
                             cudaFuncAttributeMaxDynamicSharedMemorySize, GEMM_SMEM);
        cudaFuncSetAttribute(k_gemm<HDIM, DDIM / 128, 2, false>,
                             cudaFuncAttributeMaxDynamicSharedMemorySize, GEMM_SMEM);
        cudaStreamCreateWithFlags(&s1, cudaStreamNonBlocking);
        cudaEventCreateWithFlags(&evF, cudaEventDisableTiming);
        cudaEventCreateWithFlags(&ev1, cudaEventDisableTiming);
        cudaEventCreateWithFlags(&ev2, cudaEventDisableTiming);
        init_done = true;
    }

    __half* w1h; __half* w2h; __half* xh; __half* hh; float* b1u; float* b2u;
    cudaGetSymbolAddress((void**)&w1h, g_w1h);
    cudaGetSymbolAddress((void**)&w2h, g_w2h);
    cudaGetSymbolAddress((void**)&xh,  g_xh);
    cudaGetSymbolAddress((void**)&hh,  g_h);
    cudaGetSymbolAddress((void**)&b1u, g_b1u);
    cudaGetSymbolAddress((void**)&b2u, g_b2u);

    const int CVT_GRID = (int)((size_t)(EXP + 1) * EW_STRIDE / 8 / 256);  // 18432

    // fork: weight conversions on side stream, routing on main stream
    cudaEventRecord(evF, 0);
    cudaStreamWaitEvent(s1, evF, 0);
    k_cvt<<<CVT_GRID, 256, 0, s1>>>(W1, Ws1, w1h);
    cudaEventRecord(ev1, s1);
    k_cvt<<<CVT_GRID, 256, 0, s1>>>(W2, Ws2, w2h);
    cudaEventRecord(ev2, s1);

    k_init<<<T_TOK * DDIM / 4 / 256, 256>>>(b1, bs1, b2, bs2, out);
    k_gate<<<T_TOK * 32 / 256, 256>>>(x, Wg, bg, bias);
    k_seg<<<1, 32>>>();
    k_scatter<<<T_TOK / 256, 256>>>();
    k_xh<<<TOTAL_ROWS, 128>>>(x);

    // join: GEMM1 needs W1h; GEMM2 needs W2h (combine fused into its epilogue)
    cudaStreamWaitEvent(0, ev1, 0);
    k_gemm<DDIM, HDIM / 128, 1, true ><<<PGRID, 128, GEMM_SMEM>>>(xh, w1h, b1u, nullptr, HDIM);
    cudaStreamWaitEvent(0, ev2, 0);
    k_gemm<HDIM, DDIM / 128, 2, false><<<PGRID, 128, GEMM_SMEM>>>(hh, w2h, b2u, out, DDIM);
}